// round 11
// baseline (speedup 1.0000x reference)
#include <cuda_runtime.h>
#include <cuda_bf16.h>

// Bilateral filter 5x5, sigma_xy = sigma_z = 1, zero padding.
// X: [NC, 512, 512] fp32 (NC = 12), out same shape.
//
// R10 -> R11: keep pixel-pair vectorization (2 adjacent px per thread in
// f32x2 lanes, LDS.64 row segments); FLATTEN THE DEPENDENCY GRAPH:
//  * 6 independent accumulator chains (EX2 classes d2=1,2,4,5 + poly 5,8)
//    instead of one num2/den2 chain of 24 serial FFMA2s.
//  * EX2 arg = p * fma(L,p,b)  (no L*d2 addend; spatial weight folded into
//    the per-class merge as immediate-multiplier FFMA, rt=1).
//  * poly chains unweighted; E and W applied once at merge -> poly taps do
//    not depend on E; E's EX2 issues first, consumed last.
// Diagnosis: all rounds pinned at ~48k cyc with no pipe >50% busy at any
// occupancy => serial-accumulator latency bound. This restores R4's ILP at
// R10's lower slot count.

#define TX   32
#define TYW  8
#define BW   (TX*2)           // 64 output cols per block
#define HALO 2
#define SW   (BW + 2*HALO)    // 68
#define SH   (TYW + 2*HALO)   // 12

typedef unsigned long long ull;

__device__ __forceinline__ ull pack2(float a, float b) {
    ull r; asm("mov.b64 %0, {%1, %2};" : "=l"(r) : "f"(a), "f"(b)); return r;
}
__device__ __forceinline__ void unpack2(ull v, float& a, float& b) {
    asm("mov.b64 {%0, %1}, %2;" : "=f"(a), "=f"(b) : "l"(v));
}
__device__ __forceinline__ ull fma2(ull a, ull b, ull c) {
    ull d; asm("fma.rn.f32x2 %0, %1, %2, %3;" : "=l"(d) : "l"(a), "l"(b), "l"(c)); return d;
}
__device__ __forceinline__ ull add2(ull a, ull b) {
    ull d; asm("add.rn.f32x2 %0, %1, %2;" : "=l"(d) : "l"(a), "l"(b)); return d;
}
__device__ __forceinline__ ull mul2(ull a, ull b) {
    ull d; asm("mul.rn.f32x2 %0, %1, %2;" : "=l"(d) : "l"(a), "l"(b)); return d;
}
__device__ __forceinline__ float ex2f(float a) {
    float s; asm("ex2.approx.ftz.f32 %0, %1;" : "=f"(s) : "f"(a)); return s;
}
// (hi of a, lo of b)
__device__ __forceinline__ ull mixhl(ull a, ull b) {
    float a0, a1, b0, b1;
    unpack2(a, a0, a1); unpack2(b, b0, b1);
    return pack2(a1, b0);
}

// L = -0.5*log2(e)
#define LCONST  (-0.72134752044448170f)
#define NEG2L   (1.44269504088896340f)
// degree-3 Chebyshev approx of e^{-u/2} on [0,1]
#define PK0 (0.99999770f)
#define PK1 (-0.49942563f)
#define PK2 (0.12219345f)
#define PK3 (-0.01622403f)
// spatial weights e^{-d2/2}
#define W1C (0.60653065971f)
#define W2C (0.36787944117f)
#define W4C (0.13533528324f)
#define W5C (0.08208499862f)
#define W8C (0.01831563889f)

__global__ __launch_bounds__(TX * TYW)
void bilateral_kernel(const float* __restrict__ X, float* __restrict__ out)
{
    __shared__ __align__(8) float tile[SH][SW];

    const int H = 512, W = 512;
    const int z = blockIdx.z;
    const float* __restrict__ img = X + (size_t)z * H * W;

    const int gx0 = blockIdx.x * BW - HALO;
    const int gy0 = blockIdx.y * TYW - HALO;

    // Cooperative halo load: 12*68 = 816 elements, 256 threads (4 iters).
    const int tid = threadIdx.y * TX + threadIdx.x;
    #pragma unroll
    for (int i = tid; i < SH * SW; i += TX * TYW) {
        const int sy = i / SW;
        const int sx = i - sy * SW;
        const int gx = gx0 + sx;
        const int gy = gy0 + sy;
        float v = 0.0f;
        if ((unsigned)gx < (unsigned)W && (unsigned)gy < (unsigned)H)
            v = img[gy * W + gx];
        tile[sy][sx] = v;
    }
    __syncthreads();

    const int tx   = threadIdx.x;
    const int tyr  = threadIdx.y;
    const int col0 = 2 * tx;

    // center pair (8B aligned)
    const ull c2 = *(const ull*)&tile[tyr + 2][col0 + 2];
    float c0, c1; unpack2(c2, c0, c1);

    const ull L2c = pack2(LCONST, LCONST);
    const ull b2  = mul2(c2, pack2(NEG2L, NEG2L));
    const ull cn2 = c2 ^ 0x8000000080000000ULL;   // packed negate
    // E = e^{c^2/2}; issued first, consumed only at the final merge.
    const float E0 = ex2f((-LCONST) * (c0 * c0));
    const float E1 = ex2f((-LCONST) * (c1 * c1));

    const ull K3 = pack2(PK3, PK3);
    const ull K2 = pack2(PK2, PK2);
    const ull K1 = pack2(PK1, PK1);
    const ull K0 = pack2(PK0, PK0);

    // 6 independent chains (num,den packed pairs)
    ull a1n, a1d, a2n, a2d, a4n, a4d, a5n, a5d, p5n, p5d, p8n, p8d;

    // EX2 tap: s = exp2(L*p^2 + b*p) = e^{-(p-c)^2/2} * E  (E-scaled)
    #define EX2_S(P2, S2)                                      \
        ull S2;                                                \
        {                                                      \
            const ull t2 = fma2(L2c, P2, b2);                  \
            const ull a2_ = mul2(P2, t2);                      \
            float x0, x1; unpack2(a2_, x0, x1);                \
            S2 = pack2(ex2f(x0), ex2f(x1));                    \
        }
    #define EX2_I(P2, CN, CD) { EX2_S(P2, s2_) CN = mul2(s2_, P2); CD = s2_; }
    #define EX2_A(P2, CN, CD) { EX2_S(P2, s2_) CN = fma2(s2_, P2, CN); CD = add2(CD, s2_); }

    // poly tap: s = poly(diff^2) ~= e^{-diff^2/2}  (unweighted, not E-scaled)
    #define POLY_S(P2, S2)                                     \
        ull S2;                                                \
        {                                                      \
            const ull dv = add2(P2, cn2);                      \
            const ull u2 = mul2(dv, dv);                       \
            S2 = fma2(u2, K3, K2);                             \
            S2 = fma2(u2, S2, K1);                             \
            S2 = fma2(u2, S2, K0);                             \
        }
    #define POLY_I(P2, CN, CD) { POLY_S(P2, s2_) CN = mul2(s2_, P2); CD = s2_; }
    #define POLY_A(P2, CN, CD) { POLY_S(P2, s2_) CN = fma2(s2_, P2, CN); CD = add2(CD, s2_); }

    // load row rr: 3 aligned LDS.64 + 2 mixes -> tap pairs a..e (dx 0..4)
    #define LOADROW(rr, N)                                     \
        const ull N##a = *(const ull*)&tile[rr][col0];         \
        const ull N##c = *(const ull*)&tile[rr][col0 + 2];     \
        const ull N##e = *(const ull*)&tile[rr][col0 + 4];     \
        const ull N##b = mixhl(N##a, N##c);                    \
        const ull N##d = mixhl(N##c, N##e);

    // dy=1:  d2 = 5,2,1,2,5
    { LOADROW(tyr + 1, r1)
      EX2_I(r1a, a5n, a5d) EX2_I(r1b, a2n, a2d) EX2_I(r1c, a1n, a1d)
      EX2_A(r1d, a2n, a2d) EX2_A(r1e, a5n, a5d) }
    // dy=3:  d2 = 5,2,1,2,5
    { LOADROW(tyr + 3, r3)
      EX2_A(r3a, a5n, a5d) EX2_A(r3b, a2n, a2d) EX2_A(r3c, a1n, a1d)
      EX2_A(r3d, a2n, a2d) EX2_A(r3e, a5n, a5d) }
    // dy=2:  d2 = 4,1,(0),1,4
    { const ull r2a = *(const ull*)&tile[tyr + 2][col0];
      const ull r2e = *(const ull*)&tile[tyr + 2][col0 + 4];
      const ull r2b = mixhl(r2a, c2);
      const ull r2d = mixhl(c2, r2e);
      EX2_I(r2a, a4n, a4d) EX2_A(r2b, a1n, a1d)
      EX2_A(r2d, a1n, a1d) EX2_A(r2e, a4n, a4d) }
    // dy=0:  d2 = 8,5,4,5,8
    { LOADROW(tyr + 0, r0)
      POLY_I(r0a, p8n, p8d) POLY_I(r0b, p5n, p5d) EX2_A(r0c, a4n, a4d)
      POLY_A(r0d, p5n, p5d) POLY_A(r0e, p8n, p8d) }
    // dy=4:  d2 = 8,5,4,5,8
    { LOADROW(tyr + 4, r4)
      POLY_A(r4a, p8n, p8d) POLY_A(r4b, p5n, p5d) EX2_A(r4c, a4n, a4d)
      POLY_A(r4d, p5n, p5d) POLY_A(r4e, p8n, p8d) }

    #undef EX2_S
    #undef EX2_I
    #undef EX2_A
    #undef POLY_S
    #undef POLY_I
    #undef POLY_A
    #undef LOADROW

    // ---- merge (scalar, immediate-weight FFMAs, rt=1) ----
    // EX2 chains are E-scaled; poly+center get E applied explicitly.
    float v0, v1;
    float exN0, exN1, exD0, exD1, pN0, pN1, pD0, pD1;

    unpack2(a1n, v0, v1); exN0 = W1C * v0;            exN1 = W1C * v1;
    unpack2(a2n, v0, v1); exN0 = fmaf(W2C, v0, exN0); exN1 = fmaf(W2C, v1, exN1);
    unpack2(a4n, v0, v1); exN0 = fmaf(W4C, v0, exN0); exN1 = fmaf(W4C, v1, exN1);
    unpack2(a5n, v0, v1); exN0 = fmaf(W5C, v0, exN0); exN1 = fmaf(W5C, v1, exN1);

    unpack2(a1d, v0, v1); exD0 = W1C * v0;            exD1 = W1C * v1;
    unpack2(a2d, v0, v1); exD0 = fmaf(W2C, v0, exD0); exD1 = fmaf(W2C, v1, exD1);
    unpack2(a4d, v0, v1); exD0 = fmaf(W4C, v0, exD0); exD1 = fmaf(W4C, v1, exD1);
    unpack2(a5d, v0, v1); exD0 = fmaf(W5C, v0, exD0); exD1 = fmaf(W5C, v1, exD1);

    unpack2(p8n, v0, v1); pN0 = fmaf(W8C, v0, c0);    pN1 = fmaf(W8C, v1, c1);
    unpack2(p5n, v0, v1); pN0 = fmaf(W5C, v0, pN0);   pN1 = fmaf(W5C, v1, pN1);

    unpack2(p8d, v0, v1); pD0 = fmaf(W8C, v0, 1.0f);  pD1 = fmaf(W8C, v1, 1.0f);
    unpack2(p5d, v0, v1); pD0 = fmaf(W5C, v0, pD0);   pD1 = fmaf(W5C, v1, pD1);

    const float num0 = fmaf(E0, pN0, exN0);
    const float num1 = fmaf(E1, pN1, exN1);
    const float den0 = fmaf(E0, pD0, exD0);
    const float den1 = fmaf(E1, pD1, exD1);

    float2 res;
    res.x = __fdividef(num0, den0);
    res.y = __fdividef(num1, den1);

    const int gx = blockIdx.x * BW + col0;
    const int gy = blockIdx.y * TYW + tyr;
    *(float2*)&out[(size_t)z * H * W + gy * W + gx] = res;
}

extern "C" void kernel_launch(void* const* d_in, const int* in_sizes, int n_in,
                              void* d_out, int out_size)
{
    const float* X = (const float*)d_in[0];
    float* out = (float*)d_out;

    const int H = 512, W = 512;
    const int NC = in_sizes[0] / (H * W);   // 12 for (4,3,512,512)

    dim3 block(TX, TYW);
    dim3 grid(W / BW, H / TYW, NC);
    bilateral_kernel<<<grid, block>>>(X, out);
}

// round 12
// speedup vs baseline: 1.1563x; 1.1563x over previous
#include <cuda_runtime.h>
#include <cuda_bf16.h>

// Bilateral filter 5x5, sigma_xy = sigma_z = 1, zero padding.
// X: [NC, 512, 512] fp32 (NC = 12), out same shape.
//
// R11 -> R12: SEPARABLE SHIFTABLE BILATERAL (algorithm change).
//   e^{-(p-c)^2/2} = e^{-p^2/2} e^{-c^2/2} e^{pc};  e^{-c^2/2} cancels in num/den.
//   e^{x} on [0,1] ~ deg-4 Chebyshev (err ~5e-5):  e^{pc} ~ sum A_m (pc)^m.
//   => den = sum A_m c^m V_m,  num = sum A_m c^m V_{m+1},
//      V_m = conv2D(w_spatial, e^{-p^2/2} p^m)  -- 6 fields, separable conv.
//   Zero padding is exact: pad pixel -> fields (1,0,0,0,0,0).
// Stages per block (64x16 outputs, 256 threads):
//   A: p tile (68x20) to smem.  B: fused q + horizontal 5-tap conv of the
//   6 fields at pixel-pair positions -> Hs smem.  C: vertical 5-tap conv
//   (symmetric) + packed Horner in c + divide.
// EX2/px: 25 -> ~6.3; MACs/px ~75 vs ~160; slots/SM ~79k vs R4's 107k.

#define IW 512
#define IH 512
#define BW 64
#define BH 16
#define PW (BW + 4)   // 68
#define PH (BH + 4)   // 20

typedef unsigned long long ull;

__device__ __forceinline__ ull pack2(float a, float b) {
    ull r; asm("mov.b64 %0, {%1, %2};" : "=l"(r) : "f"(a), "f"(b)); return r;
}
__device__ __forceinline__ void unpack2(ull v, float& a, float& b) {
    asm("mov.b64 {%0, %1}, %2;" : "=f"(a), "=f"(b) : "l"(v));
}
__device__ __forceinline__ ull fma2(ull a, ull b, ull c) {
    ull d; asm("fma.rn.f32x2 %0, %1, %2, %3;" : "=l"(d) : "l"(a), "l"(b), "l"(c)); return d;
}
__device__ __forceinline__ ull add2(ull a, ull b) {
    ull d; asm("add.rn.f32x2 %0, %1, %2;" : "=l"(d) : "l"(a), "l"(b)); return d;
}
__device__ __forceinline__ ull mul2(ull a, ull b) {
    ull d; asm("mul.rn.f32x2 %0, %1, %2;" : "=l"(d) : "l"(a), "l"(b)); return d;
}
__device__ __forceinline__ float ex2f(float a) {
    float s; asm("ex2.approx.ftz.f32 %0, %1;" : "=f"(s) : "f"(a)); return s;
}
// (hi of a, lo of b)
__device__ __forceinline__ ull mixhl(ull a, ull b) {
    float a0, a1, b0, b1;
    unpack2(a, a0, a1); unpack2(b, b0, b1);
    return pack2(a1, b0);
}

// L = -0.5*log2(e):  e^{-p^2/2} = exp2(L*p^2)
#define LCONST (-0.72134752044448170f)
// 1D spatial weights e^{-k^2/2}, k = -2..2 (symmetric)
#define WAC (0.13533528324f)   // |k|=2
#define WBC (0.60653065971f)   // |k|=1
// deg-4 Chebyshev of e^x on [0,1] (max err ~5e-5)
#define A0C (1.00004084f)
#define A1C (0.99859760f)
#define A2C (0.51009870f)
#define A3C (0.13997540f)
#define A4C (0.06955520f)

__global__ __launch_bounds__(256)
void bilateral_kernel(const float* __restrict__ X, float* __restrict__ out)
{
    __shared__ __align__(8) float pt[PH][PW];
    __shared__ ull Hs[PH][6][BW / 2];   // horizontal-conv fields, pixel-pairs

    const int z = blockIdx.z;
    const float* __restrict__ img = X + (size_t)z * IH * IW;
    const int gx0 = blockIdx.x * BW - 2;
    const int gy0 = blockIdx.y * BH - 2;
    const int tid = threadIdx.x;

    // ---- Stage A: p tile with zero pad ----
    #pragma unroll
    for (int i = tid; i < PH * PW; i += 256) {
        const int sy = i / PW;
        const int sx = i - sy * PW;
        const int gx = gx0 + sx;
        const int gy = gy0 + sy;
        float v = 0.0f;
        if ((unsigned)gx < IW && (unsigned)gy < IH) v = img[gy * IW + gx];
        pt[sy][sx] = v;
    }
    __syncthreads();

    const ull L2  = pack2(LCONST, LCONST);
    const ull WA2 = pack2(WAC, WAC);
    const ull WB2 = pack2(WBC, WBC);

    // ---- Stage B: q + horizontal conv, pixel-pair positions (32 x PH) ----
    #pragma unroll
    for (int i = tid; i < 32 * PH; i += 256) {
        const int row  = i >> 5;
        const int cpiB = i & 31;
        const int cp   = cpiB * 2;

        // window p cols for outputs (cp, cp+1): cp .. cp+5
        const ull P0 = *(const ull*)&pt[row][cp];
        const ull P1 = *(const ull*)&pt[row][cp + 2];
        const ull P2 = *(const ull*)&pt[row][cp + 4];
        const ull T1 = mixhl(P0, P1);
        const ull T3 = mixhl(P1, P2);

        const ull z2 = pack2(0.0f, 0.0f);
        ull h0 = z2, h1 = z2, h2 = z2, h3 = z2, h4 = z2, h5 = z2;

        // one horizontal tap: q = wx * e^{-f^2/2}; fields h_m += q * f^m
        #define BTAP(T, WM) {                                   \
            const ull u2 = mul2(T, T);                          \
            const ull a2 = mul2(u2, L2);                        \
            float aa, ab; unpack2(a2, aa, ab);                  \
            ull t2 = pack2(ex2f(aa), ex2f(ab));                 \
            WM                                                  \
            h0 = add2(h0, t2); t2 = mul2(t2, T);                \
            h1 = add2(h1, t2); t2 = mul2(t2, T);                \
            h2 = add2(h2, t2); t2 = mul2(t2, T);                \
            h3 = add2(h3, t2); t2 = mul2(t2, T);                \
            h4 = add2(h4, t2); t2 = mul2(t2, T);                \
            h5 = add2(h5, t2); }
        BTAP(P0, t2 = mul2(t2, WA2);)
        BTAP(T1, t2 = mul2(t2, WB2);)
        BTAP(P1, )
        BTAP(T3, t2 = mul2(t2, WB2);)
        BTAP(P2, t2 = mul2(t2, WA2);)
        #undef BTAP

        Hs[row][0][cpiB] = h0;
        Hs[row][1][cpiB] = h1;
        Hs[row][2][cpiB] = h2;
        Hs[row][3][cpiB] = h3;
        Hs[row][4][cpiB] = h4;
        Hs[row][5][cpiB] = h5;
    }
    __syncthreads();

    // ---- Stage C: vertical conv (2 output rows) + Horner + divide ----
    const int cpi = tid & 31;
    const int cp  = cpi * 2;
    const int ry  = (tid >> 5) * 2;     // output rows ry, ry+1

    ull V0m[6], V1m[6];
    #pragma unroll
    for (int m = 0; m < 6; m++) {
        const ull g0 = Hs[ry + 0][m][cpi];
        const ull g1 = Hs[ry + 1][m][cpi];
        const ull g2 = Hs[ry + 2][m][cpi];
        const ull g3 = Hs[ry + 3][m][cpi];
        const ull g4 = Hs[ry + 4][m][cpi];
        const ull g5 = Hs[ry + 5][m][cpi];
        V0m[m] = fma2(WA2, add2(g0, g4), fma2(WB2, add2(g1, g3), g2));
        V1m[m] = fma2(WA2, add2(g1, g5), fma2(WB2, add2(g2, g4), g3));
    }

    const ull A0_2 = pack2(A0C, A0C);
    const ull A1_2 = pack2(A1C, A1C);
    const ull A2_2 = pack2(A2C, A2C);
    const ull A3_2 = pack2(A3C, A3C);
    const ull A4_2 = pack2(A4C, A4C);

    #define OUTPAIR(Vm, K) {                                            \
        const ull c2 = *(const ull*)&pt[ry + (K) + 2][cp + 2];          \
        ull td = mul2(A4_2, Vm[4]);                                     \
        td = fma2(c2, td, mul2(A3_2, Vm[3]));                           \
        td = fma2(c2, td, mul2(A2_2, Vm[2]));                           \
        td = fma2(c2, td, mul2(A1_2, Vm[1]));                           \
        const ull den2 = fma2(c2, td, mul2(A0_2, Vm[0]));               \
        ull tn = mul2(A4_2, Vm[5]);                                     \
        tn = fma2(c2, tn, mul2(A3_2, Vm[4]));                           \
        tn = fma2(c2, tn, mul2(A2_2, Vm[3]));                           \
        tn = fma2(c2, tn, mul2(A1_2, Vm[2]));                           \
        const ull num2 = fma2(c2, tn, mul2(A0_2, Vm[1]));               \
        float n0, n1, d0, d1;                                           \
        unpack2(num2, n0, n1); unpack2(den2, d0, d1);                   \
        float2 r;                                                       \
        r.x = __fdividef(n0, d0);                                       \
        r.y = __fdividef(n1, d1);                                       \
        const int gx = blockIdx.x * BW + cp;                            \
        const int gy = blockIdx.y * BH + ry + (K);                      \
        *(float2*)&out[(size_t)z * IH * IW + gy * IW + gx] = r; }

    OUTPAIR(V0m, 0)
    OUTPAIR(V1m, 1)
    #undef OUTPAIR
}

extern "C" void kernel_launch(void* const* d_in, const int* in_sizes, int n_in,
                              void* d_out, int out_size)
{
    const float* X = (const float*)d_in[0];
    float* out = (float*)d_out;

    const int NC = in_sizes[0] / (IH * IW);   // 12 for (4,3,512,512)

    dim3 block(256);
    dim3 grid(IW / BW, IH / BH, NC);
    bilateral_kernel<<<grid, block>>>(X, out);
}